// round 2
// baseline (speedup 1.0000x reference)
#include <cuda_runtime.h>

// EMA over frames: out[b,0] = x[b,0]; out[b,t] = 0.99*out[b,t-1] + 0.01*x[b,t]
// Shapes fixed: B=4, T=128, N=256, D=768, fp32. Pure HBM stream (805 MB total).

#define EMA_B 4
#define EMA_T 128
#define EMA_N 256
#define EMA_D 768

__global__ void __launch_bounds__(256, 8)
ema_scan_kernel(const float4* __restrict__ x, float4* __restrict__ out)
{
    constexpr int ND4  = (EMA_N * EMA_D) / 4;   // 49152 float4 per (b,t) slab
    constexpr int TND4 = EMA_T * ND4;

    const int tid = blockIdx.x * blockDim.x + threadIdx.x;   // 0 .. B*ND4-1
    const int b   = tid / ND4;
    const int r   = tid - b * ND4;

    const float4* xp = x   + (long long)b * TND4 + r;
    float4*       op = out + (long long)b * TND4 + r;

    const float decay = 0.99f;
    const float omd   = 0.01f;

    // t = 0: copy (streaming hints: zero reuse, keep out of L2's way)
    float4 mem = __ldcs(xp);
    __stcs(op, mem);

    // t = 1..127 in batches of 4 (127 = 31*4 + 3): burst the 4 loads first
    // (guaranteed MLP=4), then the serial fma chain, then burst the 4 stores.
    int t = 1;
#pragma unroll 1
    for (int it = 0; it < 31; ++it, t += 4) {
        float4 v0 = __ldcs(xp + (long long)(t + 0) * ND4);
        float4 v1 = __ldcs(xp + (long long)(t + 1) * ND4);
        float4 v2 = __ldcs(xp + (long long)(t + 2) * ND4);
        float4 v3 = __ldcs(xp + (long long)(t + 3) * ND4);

        float4 m0, m1, m2, m3;
        m0.x = fmaf(decay, mem.x, omd * v0.x);
        m0.y = fmaf(decay, mem.y, omd * v0.y);
        m0.z = fmaf(decay, mem.z, omd * v0.z);
        m0.w = fmaf(decay, mem.w, omd * v0.w);

        m1.x = fmaf(decay, m0.x, omd * v1.x);
        m1.y = fmaf(decay, m0.y, omd * v1.y);
        m1.z = fmaf(decay, m0.z, omd * v1.z);
        m1.w = fmaf(decay, m0.w, omd * v1.w);

        m2.x = fmaf(decay, m1.x, omd * v2.x);
        m2.y = fmaf(decay, m1.y, omd * v2.y);
        m2.z = fmaf(decay, m1.z, omd * v2.z);
        m2.w = fmaf(decay, m1.w, omd * v2.w);

        m3.x = fmaf(decay, m2.x, omd * v3.x);
        m3.y = fmaf(decay, m2.y, omd * v3.y);
        m3.z = fmaf(decay, m2.z, omd * v3.z);
        m3.w = fmaf(decay, m2.w, omd * v3.w);

        __stcs(op + (long long)(t + 0) * ND4, m0);
        __stcs(op + (long long)(t + 1) * ND4, m1);
        __stcs(op + (long long)(t + 2) * ND4, m2);
        __stcs(op + (long long)(t + 3) * ND4, m3);

        mem = m3;
    }

    // tail: t = 125, 126, 127
    {
        float4 v0 = __ldcs(xp + (long long)(t + 0) * ND4);
        float4 v1 = __ldcs(xp + (long long)(t + 1) * ND4);
        float4 v2 = __ldcs(xp + (long long)(t + 2) * ND4);

        float4 m0, m1, m2;
        m0.x = fmaf(decay, mem.x, omd * v0.x);
        m0.y = fmaf(decay, mem.y, omd * v0.y);
        m0.z = fmaf(decay, mem.z, omd * v0.z);
        m0.w = fmaf(decay, mem.w, omd * v0.w);

        m1.x = fmaf(decay, m0.x, omd * v1.x);
        m1.y = fmaf(decay, m0.y, omd * v1.y);
        m1.z = fmaf(decay, m0.z, omd * v1.z);
        m1.w = fmaf(decay, m0.w, omd * v1.w);

        m2.x = fmaf(decay, m1.x, omd * v2.x);
        m2.y = fmaf(decay, m1.y, omd * v2.y);
        m2.z = fmaf(decay, m1.z, omd * v2.z);
        m2.w = fmaf(decay, m1.w, omd * v2.w);

        __stcs(op + (long long)(t + 0) * ND4, m0);
        __stcs(op + (long long)(t + 1) * ND4, m1);
        __stcs(op + (long long)(t + 2) * ND4, m2);
    }
}

extern "C" void kernel_launch(void* const* d_in, const int* in_sizes, int n_in,
                              void* d_out, int out_size)
{
    const float4* x   = (const float4*)d_in[0];
    float4*       out = (float4*)d_out;

    constexpr int total_f4 = (EMA_B * EMA_N * EMA_D) / 4;  // 196608
    constexpr int threads  = 256;
    constexpr int blocks   = total_f4 / threads;           // 768

    ema_scan_kernel<<<blocks, threads>>>(x, out);
}